// round 14
// baseline (speedup 1.0000x reference)
#include <cuda_runtime.h>
#include <cuda_fp16.h>
#include <math.h>

// ---------------------------------------------------------------------------
// 16-qubit statevector, batch 512. circuit qubit i <-> index bit (15-i).
// Layer = 16 one-qubit gates + CNOT-ladder = suffix-XOR permutation.
// State between passes: __half2(re,im), fp32 compute (f32x2 packed FMA).
// SU(2) gates: 4 floats (u00r,u00i,u01r,u01i); row1 derived inline.
// kA: pack = lo bit 0 (ungated in pass A) -> 8B vector loads/stores, two
//   rgate stages + float4 SMEM exchange; sfx8 perm folded into store address.
// kB: lane = bits 0..4, slots = bits 5..7, pack = b15 (ungated), warp = bits
//   8..11; ladder perm on bits 0..7 + b15-wrap folded into store.
// Batch split in FOUR quarters; each quarter's 8-kernel chain (incl. its own
// out-slice reduction) runs in its own stream; fork/join via events.
// ---------------------------------------------------------------------------

#define TPB 512
#define BAT 512
#define QBAT 128               // batch elements per chain
#define QTILES 1024            // tiles per chain

typedef unsigned long long u64;

__device__ __half2 g_st[(size_t)BAT * 65536];
__device__ float   g_part[BAT * 8 * 16];

// ---------------- packed f32x2 helpers ----------------
__device__ __forceinline__ u64 pk2(float x, float y) {
    u64 r; asm("mov.b64 %0,{%1,%2};" : "=l"(r) : "f"(x), "f"(y)); return r;
}
__device__ __forceinline__ void upk2(u64 v, float& x, float& y) {
    asm("mov.b64 {%0,%1},%2;" : "=f"(x), "=f"(y) : "l"(v));
}
__device__ __forceinline__ u64 bc2(float x) { return pk2(x, x); }
__device__ __forceinline__ u64 f2mul(u64 a, u64 b) {
    u64 r; asm("mul.rn.f32x2 %0,%1,%2;" : "=l"(r) : "l"(a), "l"(b)); return r;
}
__device__ __forceinline__ u64 f2fma(u64 a, u64 b, u64 c) {
    u64 r; asm("fma.rn.f32x2 %0,%1,%2,%3;" : "=l"(r) : "l"(a), "l"(b), "l"(c)); return r;
}
__device__ __forceinline__ u64 shfl2x(u64 v, int m) {
    float x, y; upk2(v, x, y);
    x = __shfl_xor_sync(0xffffffffu, x, m);
    y = __shfl_xor_sync(0xffffffffu, y, m);
    return pk2(x, y);
}
__device__ __forceinline__ void ld_h2(const __half2* p, float& re, float& im) {
    float2 v = __half22float2(*p); re = v.x; im = v.y;
}
__device__ __forceinline__ void st_h2(__half2* p, float re, float im) {
    *p = __floats2half2_rn(re, im);
}
__device__ __forceinline__ float2 cmulf(float2 a, float2 b) {
    return make_float2(a.x * b.x - a.y * b.y, a.x * b.y + a.y * b.x);
}
__device__ __forceinline__ int sfx5(int v) {
    v ^= v >> 1; v ^= v >> 2; v ^= v >> 4; return v & 31;
}

// SU(2) gate U = Ry(p2)*Rx(p1)*Rz(p0): store row0 only (u00r,u00i,u01r,u01i)
__device__ __forceinline__ void compute_gate4(const float* __restrict__ par,
                                              int layer, int cq, float* uo) {
    const float* pp = par + ((layer * 16 + cq) * 3);
    float sz, cz, sx, cx_, sy, cy;
    sincosf(0.5f * pp[0], &sz, &cz);
    sincosf(0.5f * pp[1], &sx, &cx_);
    sincosf(0.5f * pp[2], &sy, &cy);
    float M00r =  cx_ * cz, M00i = -cx_ * sz;
    float M01r =  sx  * sz, M01i = -sx  * cz;
    float M10r = -sx  * sz, M10i = -sx  * cz;
    float M11r =  cx_ * cz, M11i =  cx_ * sz;
    uo[0] = cy * M00r - sy * M10r;  uo[1] = cy * M00i - sy * M10i;
    uo[2] = cy * M01r - sy * M11r;  uo[3] = cy * M01i - sy * M11i;
}

// packed SU(2) gate on slot bit B
template<int B>
__device__ __forceinline__ void rgateP4(u64* VR, u64* VI, const float* __restrict__ u) {
    const u64 U0 = bc2(u[0]), U1 = bc2(u[1]), N1 = bc2(-u[1]);
    const u64 U2 = bc2(u[2]), N2 = bc2(-u[2]);
    const u64 U3 = bc2(u[3]), N3 = bc2(-u[3]);
    #pragma unroll
    for (int s = 0; s < 8; ++s) if (!(s & B)) {
        u64 ar = VR[s], ai = VI[s], br = VR[s | B], bi = VI[s | B];
        VR[s]     = f2fma(N3, bi, f2fma(U2, br, f2fma(N1, ai, f2mul(U0, ar))));
        VI[s]     = f2fma(U3, br, f2fma(U2, bi, f2fma(U1, ar, f2mul(U0, ai))));
        VR[s | B] = f2fma(U1, bi, f2fma(U0, br, f2fma(N3, ai, f2mul(N2, ar))));
        VI[s | B] = f2fma(N1, br, f2fma(U0, bi, f2fma(U3, ar, f2mul(N2, ai))));
    }
}

// packed SU(2) gate on lane bit j (shfl butterfly)
__device__ __forceinline__ void lgateP4(u64* VR, u64* VI, const float* __restrict__ u,
                                        int lane, int j) {
    const int hi = (lane >> j) & 1;
    const float cai = hi ? -u[1] : u[1];
    const float cbr = hi ? -u[2] : u[2];
    const u64 CAR = bc2(u[0]), CAI = bc2(cai), NAI = bc2(-cai);
    const u64 CBR = bc2(cbr), CBI = bc2(u[3]), NBI = bc2(-u[3]);
    #pragma unroll
    for (int s = 0; s < 8; ++s) {
        u64 pr = shfl2x(VR[s], 1 << j), pi = shfl2x(VI[s], 1 << j);
        u64 nr = f2fma(NBI, pi, f2fma(CBR, pr, f2fma(NAI, VI[s], f2mul(CAR, VR[s]))));
        u64 ni = f2fma(CBI, pr, f2fma(CBR, pi, f2fma(CAI, VR[s], f2mul(CAR, VI[s]))));
        VR[s] = nr; VI[s] = ni;
    }
}

// pass-B gates: rgate bits 5,6,7 + lgate bits 0..4 (pack = b15, never gated)
__device__ __forceinline__ void kb_gates(u64* VR, u64* VI, const float* gU, int lane) {
    rgateP4<1>(VR, VI, gU + 20);
    rgateP4<2>(VR, VI, gU + 24);
    rgateP4<4>(VR, VI, gU + 28);
    #pragma unroll
    for (int j = 0; j < 5; ++j) lgateP4(VR, VI, gU + j * 4, lane, j);
}

// pass-B store with full ladder perm folded in.
__device__ __forceinline__ void kb_store(u64* VR, u64* VI, unsigned base,
                                         int cc, int w, int lane) {
    const int b8 = w & 1;
    const int S  = sfx5(lane);
    const int pl = __popc((unsigned)lane) & 1;
    #pragma unroll
    for (int k = 0; k < 8; ++k) {
        const int pk  = __popc((unsigned)k) & 1;                 // compile-time
        const int s3  = (k ^ (k >> 1) ^ (k >> 2)) & 7;           // sfx3(k), ct
        int flip = pk ^ b8;                                      // warp-uniform
        int dlo  = S ^ (flip ? 31 : 0);
        int dh3  = s3 ^ (b8 ? 7 : 0);
        int d0   = pl ^ flip;                                    // per lane
        float r0, r1, i0, i1;
        upk2(VR[k], r0, r1); upk2(VI[k], i0, i1);
        float Ar = d0 ? r1 : r0, Ai = d0 ? i1 : i0;              // dest b15'=0
        float Br = d0 ? r0 : r1, Bi = d0 ? i0 : i1;              // dest b15'=1
        unsigned a = base | (cc << 12) | (w << 8) | (dh3 << 5) | dlo;
        st_h2(&g_st[a], Ar, Ai);
        st_h2(&g_st[a | 0x8000u], Br, Bi);
    }
}

// ---------------------------------------------------------------------------
// Pass A (layers 1..3), PERSISTENT over one quarter-batch (1024 tiles).
// Tile = bits {0..4} U {8..15}, c3 = 5..7, pack = bit 0 (ungated).
// ---------------------------------------------------------------------------
__global__ void __launch_bounds__(TPB, 2) kA(const float* __restrict__ par,
                                             int layer, int boff) {
    extern __shared__ float4 buf4[];              // 4096 float4 = 64KB
    float* gUA = (float*)(buf4 + 4096);           // 32 floats

    const int tid = threadIdx.x, lane = tid & 31, w = tid >> 5;
    if (tid < 8) compute_gate4(par, layer, 7 - tid, gUA + tid * 4);  // bit 8+j
    __syncthreads();

    const int llo = lane & 15, bh = lane >> 4;        // bh = b8 (st1) / b12 (st2)
    const int wbase = bh * 256 + w * 16 + llo;        // write: [(k<<1)|b8][w][llo]
    const int rbase = w * 256 + bh * 16 + llo;        // read:  [w][(k<<1)|b12][llo]
    int R = w | (bh << 4);                            // stage2 hi bits 8..12
    int GR = R ^ (R >> 1); GR ^= GR >> 2; GR ^= GR >> 4;  // sfx8(R)

    for (int t = blockIdx.x; t < QTILES; t += gridDim.x) {
        const int c3 = t & 7;
        const unsigned base = (unsigned)((t >> 3) + boff) << 16;
        const unsigned aL = base | (w << 12) | (bh << 8) | (c3 << 5) | (llo << 1);

        u64 VR[8], VI[8];
        #pragma unroll
        for (int k = 0; k < 8; ++k) {
            uint2 raw = *reinterpret_cast<const uint2*>(g_st + (aL | (k << 9)));
            float2 f0 = __half22float2(*reinterpret_cast<__half2*>(&raw.x));
            float2 f1 = __half22float2(*reinterpret_cast<__half2*>(&raw.y));
            VR[k] = pk2(f0.x, f1.x); VI[k] = pk2(f0.y, f1.y);
        }

        // stage1: bits 9,10,11 (rgate) + bit 8 (lane gate j=4)
        rgateP4<1>(VR, VI, gUA + 4);
        rgateP4<2>(VR, VI, gUA + 8);
        rgateP4<4>(VR, VI, gUA + 12);
        lgateP4(VR, VI, gUA + 0, lane, 4);

        __syncthreads();     // buf4 free (prev iteration's readers done)
        #pragma unroll
        for (int k = 0; k < 8; ++k) {
            float r0, r1, i0, i1;
            upk2(VR[k], r0, r1); upk2(VI[k], i0, i1);
            buf4[wbase + k * 512] = make_float4(r0, i0, r1, i1);
        }
        __syncthreads();
        #pragma unroll
        for (int k = 0; k < 8; ++k) {
            float4 v = buf4[rbase + k * 32];
            VR[k] = pk2(v.x, v.z); VI[k] = pk2(v.y, v.w);
        }

        // stage2: bits 13,14,15 (rgate) + bit 12 (lane gate j=4)
        rgateP4<1>(VR, VI, gUA + 20);
        rgateP4<2>(VR, VI, gUA + 24);
        rgateP4<4>(VR, VI, gUA + 28);
        lgateP4(VR, VI, gUA + 16, lane, 4);

        // store: dest hi byte = GR ^ sfx8(k<<5); lo bits unchanged (8B store)
        const unsigned D0 = base | ((unsigned)GR << 8) | (c3 << 5) | (llo << 1);
        #pragma unroll
        for (int k = 0; k < 8; ++k) {
            int e = k << 5; e ^= e >> 1; e ^= e >> 2; e ^= e >> 4;   // ct
            unsigned idx = D0 ^ ((unsigned)e << 8);
            float r0, r1, i0, i1;
            upk2(VR[k], r0, r1); upk2(VI[k], i0, i1);
            __half2 ha = __floats2half2_rn(r0, i0);
            __half2 hb = __floats2half2_rn(r1, i1);
            uint2 o;
            o.x = *reinterpret_cast<unsigned*>(&ha);
            o.y = *reinterpret_cast<unsigned*>(&hb);
            *reinterpret_cast<uint2*>(g_st + idx) = o;
        }
    }
}

// ---------------------------------------------------------------------------
// kB0 (layer 0): ONE CTA PER BATCH ELEMENT of its quarter. Product tables
// built once, then loop the 8 cc-tiles: synthesize, lo gates, perm store.
// ---------------------------------------------------------------------------
__global__ void __launch_bounds__(TPB, 2) kB0(const float* __restrict__ x,
                                              const float* __restrict__ par,
                                              int boff) {
    __shared__ float4 fv[16];
    __shared__ float  gU[32];
    __shared__ float2 Tlo[256], Thi[256];

    const int tid = threadIdx.x, lane = tid & 31, w = tid >> 5;  // w = bits 8..11
    const int b   = blockIdx.x + boff;
    const unsigned base = (unsigned)b << 16;

    if (tid < 16) {
        int m = tid;                         // index bit m <-> cq 15-m
        float s, c; sincosf(0.5f * x[b * 16 + (15 - m)], &s, &c);
        if (m < 8) {
            fv[m] = make_float4(c, 0.f, 0.f, -s);          // RX|0> = (c, -i s)
        } else {
            float U[4]; compute_gate4(par, 0, 15 - m, U);  // layer-0 hi gate
            fv[m] = make_float4(U[0]*c + U[3]*s, U[1]*c - U[2]*s,
                                -U[2]*c - U[1]*s, U[3]*c - U[0]*s);
        }
    } else if (tid >= 32 && tid < 40) {
        compute_gate4(par, 0, 15 - (tid - 32), gU + (tid - 32) * 4);  // lo gates
    }
    __syncthreads();

    {   // build tables once per batch: 0..255 -> Tlo, 256..511 -> Thi
        int e = tid & 255;
        int mbase = (tid < 256) ? 0 : 8;
        float2 cacc = make_float2(1.f, 0.f);
        #pragma unroll
        for (int m = 0; m < 8; ++m) {
            float4 F = fv[mbase + m];
            float2 bb = ((e >> m) & 1) ? make_float2(F.z, F.w)
                                       : make_float2(F.x, F.y);
            cacc = cmulf(cacc, bb);
        }
        if (tid < 256) {
            Tlo[e] = cacc;
        } else {
            int d = e ^ (e >> 1); d ^= d >> 2; d ^= d >> 4;   // sfx8(e)
            Thi[d & 255] = cacc;                              // Thi[h]=F(inv(h))
        }
    }
    __syncthreads();

    #pragma unroll
    for (int cc = 0; cc < 8; ++cc) {
        u64 VR[8], VI[8];
        float2 H0 = Thi[w | (cc << 4)];
        float2 H1 = Thi[w | (cc << 4) | 128];
        #pragma unroll
        for (int k = 0; k < 8; ++k) {
            float2 L  = Tlo[(k << 5) | lane];
            float2 a0 = cmulf(H0, L), a1 = cmulf(H1, L);
            VR[k] = pk2(a0.x, a1.x); VI[k] = pk2(a0.y, a1.y);
        }
        kb_gates(VR, VI, gU, lane);
        kb_store(VR, VI, base, cc, w, lane);
    }
}

// ---------------------------------------------------------------------------
// kBmid (layers 1,2), PERSISTENT over one quarter-batch.
// ---------------------------------------------------------------------------
__global__ void __launch_bounds__(TPB, 2) kBmid(const float* __restrict__ par,
                                                int layer, int boff) {
    __shared__ float gU[32];

    const int tid = threadIdx.x, lane = tid & 31, w = tid >> 5;

    if (tid < 8) compute_gate4(par, layer, 15 - tid, gU + tid * 4);
    __syncthreads();

    for (int t = blockIdx.x; t < QTILES; t += gridDim.x) {
        const int cc = t & 7;
        const unsigned base = (unsigned)((t >> 3) + boff) << 16;

        u64 VR[8], VI[8];
        #pragma unroll
        for (int k = 0; k < 8; ++k) {
            unsigned a = base | (cc << 12) | (w << 8) | (k << 5) | lane;
            float r0, i0, r1, i1;
            ld_h2(&g_st[a], r0, i0);
            ld_h2(&g_st[a | 0x8000u], r1, i1);
            VR[k] = pk2(r0, r1); VI[k] = pk2(i0, i1);
        }

        kb_gates(VR, VI, gU, lane);
        kb_store(VR, VI, base, cc, w, lane);
    }
}

// ---------------------------------------------------------------------------
// kBlast (layer 3), PERSISTENT over one quarter-batch: <Z> partials.
// ---------------------------------------------------------------------------
__global__ void __launch_bounds__(TPB, 2) kBlast(const float* __restrict__ par,
                                                 int layer, int boff) {
    __shared__ float gU[32];
    __shared__ float red[16][17];

    const int tid = threadIdx.x, lane = tid & 31, w = tid >> 5;
    const int b8 = w & 1;

    if (tid < 8) compute_gate4(par, layer, 15 - tid, gU + tid * 4);
    __syncthreads();

    const int S  = sfx5(lane);
    const int pl = __popc((unsigned)lane) & 1;

    for (int t = blockIdx.x; t < QTILES; t += gridDim.x) {
        const int cc = t & 7;
        const int b  = (t >> 3) + boff;
        const unsigned base = (unsigned)b << 16;

        u64 VR[8], VI[8];
        #pragma unroll
        for (int k = 0; k < 8; ++k) {
            unsigned a = base | (cc << 12) | (w << 8) | (k << 5) | lane;
            float r0, i0, r1, i1;
            ld_h2(&g_st[a], r0, i0);
            ld_h2(&g_st[a | 0x8000u], r1, i1);
            VR[k] = pk2(r0, r1); VI[k] = pk2(i0, i1);
        }

        kb_gates(VR, VI, gU, lane);

        float ee[8], W0 = 0.f;
        #pragma unroll
        for (int k = 0; k < 8; ++k) {
            const int j0 = (k ^ (k >> 1) ^ (k >> 2)) & 7;
            const int pk = __popc((unsigned)k) & 1;
            float r0, r1, i0, i1;
            upk2(VR[k], r0, r1); upk2(VI[k], i0, i1);
            float p0 = r0 * r0 + i0 * i0, p1 = r1 * r1 + i1 * i1;
            ee[j0] = p0 + p1;
            W0 += pk ? (p1 - p0) : (p0 - p1);
        }
        float e04 = ee[0] + ee[4], e15 = ee[1] + ee[5];
        float e26 = ee[2] + ee[6], e37 = ee[3] + ee[7];
        float T7 = (ee[0] - ee[4]) + (ee[1] - ee[5]) + (ee[2] - ee[6]) + (ee[3] - ee[7]);
        float a0 = e04 + e26, a1 = e15 + e37;
        float T6 = (e04 - e26) + (e15 - e37);
        float T0 = a0 + a1, T5 = a0 - a1;
        if (b8) { T5 = -T5; T6 = -T6; T7 = -T7; W0 = -W0; }

        float acc[16];
        #pragma unroll
        for (int m = 0; m < 16; ++m) {
            if      (m < 5)   acc[m] = ((S >> m) & 1) ? -T5 : T5;
            else if (m == 5)  acc[m] = T5;
            else if (m == 6)  acc[m] = T6;
            else if (m == 7)  acc[m] = T7;
            else if (m < 12)  acc[m] = ((w >> (m - 8)) & 1) ? -T0 : T0;
            else if (m < 15)  acc[m] = ((cc >> (m - 12)) & 1) ? -T0 : T0;
            else              acc[m] = pl ? -W0 : W0;
        }

        #pragma unroll
        for (int m = 0; m < 16; ++m) {
            float v = acc[m];
            #pragma unroll
            for (int o = 16; o > 0; o >>= 1) v += __shfl_xor_sync(0xffffffffu, v, o);
            if (lane == 0) red[m][w] = v;
        }
        __syncthreads();
        if (tid < 16) {
            float s = 0.f;
            #pragma unroll
            for (int k = 0; k < 16; ++k) s += red[tid][k];
            g_part[(b * 8 + cc) * 16 + tid] = s;
        }
        __syncthreads();
    }
}

// per-chain final reduction over its quarter of the batch
__global__ void kBfin(float* __restrict__ out, int boff) {
    int i = blockIdx.x * blockDim.x + threadIdx.x;
    if (i < QBAT * 16) {
        int b = (i >> 4) + boff, m = i & 15;
        float s = 0.f;
        #pragma unroll
        for (int cc = 0; cc < 8; ++cc) s += g_part[(b * 8 + cc) * 16 + m];
        out[b * 16 + (15 - m)] = s;
    }
}

// ---------------------------------------------------------------------------
extern "C" void kernel_launch(void* const* d_in, const int* in_sizes, int n_in,
                              void* d_out, int out_size) {
    const float* x   = (const float*)d_in[0];
    const float* par = (const float*)d_in[1];
    if (n_in >= 2 && in_sizes[0] == 192) {
        const float* t = x; x = par; par = t;
    }
    float* out = (float*)d_out;

    int nsm = 148;
    cudaDeviceGetAttribute(&nsm, cudaDevAttrMultiProcessorCount, 0);
    const int gpersist = 2 * nsm;

    const size_t smA = 4096 * sizeof(float4) + 32 * sizeof(float);
    cudaFuncSetAttribute(kA, cudaFuncAttributeMaxDynamicSharedMemorySize, (int)smA);

    // Extra streams + fork/join events, created once on the first
    // (non-captured correctness) call; reused during graph capture.
    static cudaStream_t sx[3] = {nullptr, nullptr, nullptr};
    static cudaEvent_t  evF = nullptr;
    static cudaEvent_t  evJ[3] = {nullptr, nullptr, nullptr};
    if (sx[0] == nullptr) {
        for (int i = 0; i < 3; ++i) {
            cudaStreamCreateWithFlags(&sx[i], cudaStreamNonBlocking);
            cudaEventCreateWithFlags(&evJ[i], cudaEventDisableTiming);
        }
        cudaEventCreateWithFlags(&evF, cudaEventDisableTiming);
    }

    cudaStream_t s1 = 0;                      // legacy default (capture) stream
    cudaStream_t chains[4] = {s1, sx[0], sx[1], sx[2]};

    // fork
    cudaEventRecord(evF, s1);
    for (int i = 0; i < 3; ++i) cudaStreamWaitEvent(sx[i], evF, 0);

    // four independent quarter-batch chains
    for (int q = 0; q < 4; ++q) {
        cudaStream_t s = chains[q];
        const int boff = q * QBAT;
        kB0<<<QBAT, TPB, 0, s>>>(x, par, boff);
        for (int layer = 1; layer < 4; ++layer) {
            kA<<<gpersist, TPB, smA, s>>>(par, layer, boff);
            if (layer < 3) kBmid<<<gpersist, TPB, 0, s>>>(par, layer, boff);
            else           kBlast<<<gpersist, TPB, 0, s>>>(par, layer, boff);
        }
        kBfin<<<8, 256, 0, s>>>(out, boff);   // per-chain out slice
    }

    // join all extra streams back to s1 (capture-correct)
    for (int i = 0; i < 3; ++i) {
        cudaEventRecord(evJ[i], sx[i]);
        cudaStreamWaitEvent(s1, evJ[i], 0);
    }
}

// round 15
// speedup vs baseline: 1.0156x; 1.0156x over previous
#include <cuda_runtime.h>
#include <cuda_fp16.h>
#include <math.h>

// ---------------------------------------------------------------------------
// 16-qubit statevector, batch 512. circuit qubit i <-> index bit (15-i).
// Layer = 16 one-qubit gates + CNOT-ladder = suffix-XOR permutation.
// State between passes: __half2(re,im), fp32 compute (f32x2 packed FMA).
// SU(2) gates: 4 floats (u00r,u00i,u01r,u01i); row1 derived inline.
// kA: pack = lo bit 0 (ungated in pass A) -> 8B vector loads/stores, two
//   rgate stages + float4 SMEM exchange; sfx8 perm folded into store address.
// kB: lane = bits 0..4, slots = bits 5..7, pack = b15 (ungated), warp = bits
//   8..11; ladder perm on bits 0..7 + b15-wrap folded into store.
// Batch split in TWO halves (optimum found in R13/R14 sweep); each half's
// chain incl. its own out-slice reduction runs in its own stream.
// ---------------------------------------------------------------------------

#define TPB 512
#define BAT 512
#define HBAT 256               // batch elements per chain
#define HTILES 2048            // tiles per chain

typedef unsigned long long u64;

__device__ __half2 g_st[(size_t)BAT * 65536];
__device__ float   g_part[BAT * 8 * 16];

// ---------------- packed f32x2 helpers ----------------
__device__ __forceinline__ u64 pk2(float x, float y) {
    u64 r; asm("mov.b64 %0,{%1,%2};" : "=l"(r) : "f"(x), "f"(y)); return r;
}
__device__ __forceinline__ void upk2(u64 v, float& x, float& y) {
    asm("mov.b64 {%0,%1},%2;" : "=f"(x), "=f"(y) : "l"(v));
}
__device__ __forceinline__ u64 bc2(float x) { return pk2(x, x); }
__device__ __forceinline__ u64 f2mul(u64 a, u64 b) {
    u64 r; asm("mul.rn.f32x2 %0,%1,%2;" : "=l"(r) : "l"(a), "l"(b)); return r;
}
__device__ __forceinline__ u64 f2fma(u64 a, u64 b, u64 c) {
    u64 r; asm("fma.rn.f32x2 %0,%1,%2,%3;" : "=l"(r) : "l"(a), "l"(b), "l"(c)); return r;
}
__device__ __forceinline__ u64 shfl2x(u64 v, int m) {
    float x, y; upk2(v, x, y);
    x = __shfl_xor_sync(0xffffffffu, x, m);
    y = __shfl_xor_sync(0xffffffffu, y, m);
    return pk2(x, y);
}
__device__ __forceinline__ void ld_h2(const __half2* p, float& re, float& im) {
    float2 v = __half22float2(*p); re = v.x; im = v.y;
}
__device__ __forceinline__ void st_h2(__half2* p, float re, float im) {
    *p = __floats2half2_rn(re, im);
}
__device__ __forceinline__ float2 cmulf(float2 a, float2 b) {
    return make_float2(a.x * b.x - a.y * b.y, a.x * b.y + a.y * b.x);
}
__device__ __forceinline__ int sfx5(int v) {
    v ^= v >> 1; v ^= v >> 2; v ^= v >> 4; return v & 31;
}

// SU(2) gate U = Ry(p2)*Rx(p1)*Rz(p0): store row0 only (u00r,u00i,u01r,u01i)
__device__ __forceinline__ void compute_gate4(const float* __restrict__ par,
                                              int layer, int cq, float* uo) {
    const float* pp = par + ((layer * 16 + cq) * 3);
    float sz, cz, sx, cx_, sy, cy;
    sincosf(0.5f * pp[0], &sz, &cz);
    sincosf(0.5f * pp[1], &sx, &cx_);
    sincosf(0.5f * pp[2], &sy, &cy);
    float M00r =  cx_ * cz, M00i = -cx_ * sz;
    float M01r =  sx  * sz, M01i = -sx  * cz;
    float M10r = -sx  * sz, M10i = -sx  * cz;
    float M11r =  cx_ * cz, M11i =  cx_ * sz;
    uo[0] = cy * M00r - sy * M10r;  uo[1] = cy * M00i - sy * M10i;
    uo[2] = cy * M01r - sy * M11r;  uo[3] = cy * M01i - sy * M11i;
}

// packed SU(2) gate on slot bit B
template<int B>
__device__ __forceinline__ void rgateP4(u64* VR, u64* VI, const float* __restrict__ u) {
    const u64 U0 = bc2(u[0]), U1 = bc2(u[1]), N1 = bc2(-u[1]);
    const u64 U2 = bc2(u[2]), N2 = bc2(-u[2]);
    const u64 U3 = bc2(u[3]), N3 = bc2(-u[3]);
    #pragma unroll
    for (int s = 0; s < 8; ++s) if (!(s & B)) {
        u64 ar = VR[s], ai = VI[s], br = VR[s | B], bi = VI[s | B];
        VR[s]     = f2fma(N3, bi, f2fma(U2, br, f2fma(N1, ai, f2mul(U0, ar))));
        VI[s]     = f2fma(U3, br, f2fma(U2, bi, f2fma(U1, ar, f2mul(U0, ai))));
        VR[s | B] = f2fma(U1, bi, f2fma(U0, br, f2fma(N3, ai, f2mul(N2, ar))));
        VI[s | B] = f2fma(N1, br, f2fma(U0, bi, f2fma(U3, ar, f2mul(N2, ai))));
    }
}

// packed SU(2) gate on lane bit j (shfl butterfly)
__device__ __forceinline__ void lgateP4(u64* VR, u64* VI, const float* __restrict__ u,
                                        int lane, int j) {
    const int hi = (lane >> j) & 1;
    const float cai = hi ? -u[1] : u[1];
    const float cbr = hi ? -u[2] : u[2];
    const u64 CAR = bc2(u[0]), CAI = bc2(cai), NAI = bc2(-cai);
    const u64 CBR = bc2(cbr), CBI = bc2(u[3]), NBI = bc2(-u[3]);
    #pragma unroll
    for (int s = 0; s < 8; ++s) {
        u64 pr = shfl2x(VR[s], 1 << j), pi = shfl2x(VI[s], 1 << j);
        u64 nr = f2fma(NBI, pi, f2fma(CBR, pr, f2fma(NAI, VI[s], f2mul(CAR, VR[s]))));
        u64 ni = f2fma(CBI, pr, f2fma(CBR, pi, f2fma(CAI, VR[s], f2mul(CAR, VI[s]))));
        VR[s] = nr; VI[s] = ni;
    }
}

// pass-B gates: rgate bits 5,6,7 + lgate bits 0..4 (pack = b15, never gated)
__device__ __forceinline__ void kb_gates(u64* VR, u64* VI, const float* gU, int lane) {
    rgateP4<1>(VR, VI, gU + 20);
    rgateP4<2>(VR, VI, gU + 24);
    rgateP4<4>(VR, VI, gU + 28);
    #pragma unroll
    for (int j = 0; j < 5; ++j) lgateP4(VR, VI, gU + j * 4, lane, j);
}

// pass-B store with full ladder perm folded in.
__device__ __forceinline__ void kb_store(u64* VR, u64* VI, unsigned base,
                                         int cc, int w, int lane) {
    const int b8 = w & 1;
    const int S  = sfx5(lane);
    const int pl = __popc((unsigned)lane) & 1;
    #pragma unroll
    for (int k = 0; k < 8; ++k) {
        const int pk  = __popc((unsigned)k) & 1;                 // compile-time
        const int s3  = (k ^ (k >> 1) ^ (k >> 2)) & 7;           // sfx3(k), ct
        int flip = pk ^ b8;                                      // warp-uniform
        int dlo  = S ^ (flip ? 31 : 0);
        int dh3  = s3 ^ (b8 ? 7 : 0);
        int d0   = pl ^ flip;                                    // per lane
        float r0, r1, i0, i1;
        upk2(VR[k], r0, r1); upk2(VI[k], i0, i1);
        float Ar = d0 ? r1 : r0, Ai = d0 ? i1 : i0;              // dest b15'=0
        float Br = d0 ? r0 : r1, Bi = d0 ? i0 : i1;              // dest b15'=1
        unsigned a = base | (cc << 12) | (w << 8) | (dh3 << 5) | dlo;
        st_h2(&g_st[a], Ar, Ai);
        st_h2(&g_st[a | 0x8000u], Br, Bi);
    }
}

// ---------------------------------------------------------------------------
// Pass A (layers 1..3), PERSISTENT over one half-batch (2048 tiles).
// Tile = bits {0..4} U {8..15}, c3 = 5..7, pack = bit 0 (ungated).
// ---------------------------------------------------------------------------
__global__ void __launch_bounds__(TPB, 2) kA(const float* __restrict__ par,
                                             int layer, int boff) {
    extern __shared__ float4 buf4[];              // 4096 float4 = 64KB
    float* gUA = (float*)(buf4 + 4096);           // 32 floats

    const int tid = threadIdx.x, lane = tid & 31, w = tid >> 5;
    if (tid < 8) compute_gate4(par, layer, 7 - tid, gUA + tid * 4);  // bit 8+j
    __syncthreads();

    const int llo = lane & 15, bh = lane >> 4;        // bh = b8 (st1) / b12 (st2)
    const int wbase = bh * 256 + w * 16 + llo;        // write: [(k<<1)|b8][w][llo]
    const int rbase = w * 256 + bh * 16 + llo;        // read:  [w][(k<<1)|b12][llo]
    int R = w | (bh << 4);                            // stage2 hi bits 8..12
    int GR = R ^ (R >> 1); GR ^= GR >> 2; GR ^= GR >> 4;  // sfx8(R)

    for (int t = blockIdx.x; t < HTILES; t += gridDim.x) {
        const int c3 = t & 7;
        const unsigned base = (unsigned)((t >> 3) + boff) << 16;
        const unsigned aL = base | (w << 12) | (bh << 8) | (c3 << 5) | (llo << 1);

        u64 VR[8], VI[8];
        #pragma unroll
        for (int k = 0; k < 8; ++k) {
            uint2 raw = *reinterpret_cast<const uint2*>(g_st + (aL | (k << 9)));
            float2 f0 = __half22float2(*reinterpret_cast<__half2*>(&raw.x));
            float2 f1 = __half22float2(*reinterpret_cast<__half2*>(&raw.y));
            VR[k] = pk2(f0.x, f1.x); VI[k] = pk2(f0.y, f1.y);
        }

        // stage1: bits 9,10,11 (rgate) + bit 8 (lane gate j=4)
        rgateP4<1>(VR, VI, gUA + 4);
        rgateP4<2>(VR, VI, gUA + 8);
        rgateP4<4>(VR, VI, gUA + 12);
        lgateP4(VR, VI, gUA + 0, lane, 4);

        __syncthreads();     // buf4 free (prev iteration's readers done)
        #pragma unroll
        for (int k = 0; k < 8; ++k) {
            float r0, r1, i0, i1;
            upk2(VR[k], r0, r1); upk2(VI[k], i0, i1);
            buf4[wbase + k * 512] = make_float4(r0, i0, r1, i1);
        }
        __syncthreads();
        #pragma unroll
        for (int k = 0; k < 8; ++k) {
            float4 v = buf4[rbase + k * 32];
            VR[k] = pk2(v.x, v.z); VI[k] = pk2(v.y, v.w);
        }

        // stage2: bits 13,14,15 (rgate) + bit 12 (lane gate j=4)
        rgateP4<1>(VR, VI, gUA + 20);
        rgateP4<2>(VR, VI, gUA + 24);
        rgateP4<4>(VR, VI, gUA + 28);
        lgateP4(VR, VI, gUA + 16, lane, 4);

        // store: dest hi byte = GR ^ sfx8(k<<5); lo bits unchanged (8B store)
        const unsigned D0 = base | ((unsigned)GR << 8) | (c3 << 5) | (llo << 1);
        #pragma unroll
        for (int k = 0; k < 8; ++k) {
            int e = k << 5; e ^= e >> 1; e ^= e >> 2; e ^= e >> 4;   // ct
            unsigned idx = D0 ^ ((unsigned)e << 8);
            float r0, r1, i0, i1;
            upk2(VR[k], r0, r1); upk2(VI[k], i0, i1);
            __half2 ha = __floats2half2_rn(r0, i0);
            __half2 hb = __floats2half2_rn(r1, i1);
            uint2 o;
            o.x = *reinterpret_cast<unsigned*>(&ha);
            o.y = *reinterpret_cast<unsigned*>(&hb);
            *reinterpret_cast<uint2*>(g_st + idx) = o;
        }
    }
}

// ---------------------------------------------------------------------------
// kB0 (layer 0): ONE CTA PER BATCH ELEMENT of its half. Product tables built
// once, then loop the 8 cc-tiles: synthesize, lo gates, perm-folded store.
// ---------------------------------------------------------------------------
__global__ void __launch_bounds__(TPB, 2) kB0(const float* __restrict__ x,
                                              const float* __restrict__ par,
                                              int boff) {
    __shared__ float4 fv[16];
    __shared__ float  gU[32];
    __shared__ float2 Tlo[256], Thi[256];

    const int tid = threadIdx.x, lane = tid & 31, w = tid >> 5;  // w = bits 8..11
    const int b   = blockIdx.x + boff;
    const unsigned base = (unsigned)b << 16;

    if (tid < 16) {
        int m = tid;                         // index bit m <-> cq 15-m
        float s, c; sincosf(0.5f * x[b * 16 + (15 - m)], &s, &c);
        if (m < 8) {
            fv[m] = make_float4(c, 0.f, 0.f, -s);          // RX|0> = (c, -i s)
        } else {
            float U[4]; compute_gate4(par, 0, 15 - m, U);  // layer-0 hi gate
            fv[m] = make_float4(U[0]*c + U[3]*s, U[1]*c - U[2]*s,
                                -U[2]*c - U[1]*s, U[3]*c - U[0]*s);
        }
    } else if (tid >= 32 && tid < 40) {
        compute_gate4(par, 0, 15 - (tid - 32), gU + (tid - 32) * 4);  // lo gates
    }
    __syncthreads();

    {   // build tables once per batch: 0..255 -> Tlo, 256..511 -> Thi
        int e = tid & 255;
        int mbase = (tid < 256) ? 0 : 8;
        float2 cacc = make_float2(1.f, 0.f);
        #pragma unroll
        for (int m = 0; m < 8; ++m) {
            float4 F = fv[mbase + m];
            float2 bb = ((e >> m) & 1) ? make_float2(F.z, F.w)
                                       : make_float2(F.x, F.y);
            cacc = cmulf(cacc, bb);
        }
        if (tid < 256) {
            Tlo[e] = cacc;
        } else {
            int d = e ^ (e >> 1); d ^= d >> 2; d ^= d >> 4;   // sfx8(e)
            Thi[d & 255] = cacc;                              // Thi[h]=F(inv(h))
        }
    }
    __syncthreads();

    #pragma unroll
    for (int cc = 0; cc < 8; ++cc) {
        u64 VR[8], VI[8];
        float2 H0 = Thi[w | (cc << 4)];
        float2 H1 = Thi[w | (cc << 4) | 128];
        #pragma unroll
        for (int k = 0; k < 8; ++k) {
            float2 L  = Tlo[(k << 5) | lane];
            float2 a0 = cmulf(H0, L), a1 = cmulf(H1, L);
            VR[k] = pk2(a0.x, a1.x); VI[k] = pk2(a0.y, a1.y);
        }
        kb_gates(VR, VI, gU, lane);
        kb_store(VR, VI, base, cc, w, lane);
    }
}

// ---------------------------------------------------------------------------
// kBmid (layers 1,2), PERSISTENT over one half-batch.
// ---------------------------------------------------------------------------
__global__ void __launch_bounds__(TPB, 2) kBmid(const float* __restrict__ par,
                                                int layer, int boff) {
    __shared__ float gU[32];

    const int tid = threadIdx.x, lane = tid & 31, w = tid >> 5;

    if (tid < 8) compute_gate4(par, layer, 15 - tid, gU + tid * 4);
    __syncthreads();

    for (int t = blockIdx.x; t < HTILES; t += gridDim.x) {
        const int cc = t & 7;
        const unsigned base = (unsigned)((t >> 3) + boff) << 16;

        u64 VR[8], VI[8];
        #pragma unroll
        for (int k = 0; k < 8; ++k) {
            unsigned a = base | (cc << 12) | (w << 8) | (k << 5) | lane;
            float r0, i0, r1, i1;
            ld_h2(&g_st[a], r0, i0);
            ld_h2(&g_st[a | 0x8000u], r1, i1);
            VR[k] = pk2(r0, r1); VI[k] = pk2(i0, i1);
        }

        kb_gates(VR, VI, gU, lane);
        kb_store(VR, VI, base, cc, w, lane);
    }
}

// ---------------------------------------------------------------------------
// kBlast (layer 3), PERSISTENT over one half-batch: <Z> partials.
// ---------------------------------------------------------------------------
__global__ void __launch_bounds__(TPB, 2) kBlast(const float* __restrict__ par,
                                                 int layer, int boff) {
    __shared__ float gU[32];
    __shared__ float red[16][17];

    const int tid = threadIdx.x, lane = tid & 31, w = tid >> 5;
    const int b8 = w & 1;

    if (tid < 8) compute_gate4(par, layer, 15 - tid, gU + tid * 4);
    __syncthreads();

    const int S  = sfx5(lane);
    const int pl = __popc((unsigned)lane) & 1;

    for (int t = blockIdx.x; t < HTILES; t += gridDim.x) {
        const int cc = t & 7;
        const int b  = (t >> 3) + boff;
        const unsigned base = (unsigned)b << 16;

        u64 VR[8], VI[8];
        #pragma unroll
        for (int k = 0; k < 8; ++k) {
            unsigned a = base | (cc << 12) | (w << 8) | (k << 5) | lane;
            float r0, i0, r1, i1;
            ld_h2(&g_st[a], r0, i0);
            ld_h2(&g_st[a | 0x8000u], r1, i1);
            VR[k] = pk2(r0, r1); VI[k] = pk2(i0, i1);
        }

        kb_gates(VR, VI, gU, lane);

        float ee[8], W0 = 0.f;
        #pragma unroll
        for (int k = 0; k < 8; ++k) {
            const int j0 = (k ^ (k >> 1) ^ (k >> 2)) & 7;
            const int pk = __popc((unsigned)k) & 1;
            float r0, r1, i0, i1;
            upk2(VR[k], r0, r1); upk2(VI[k], i0, i1);
            float p0 = r0 * r0 + i0 * i0, p1 = r1 * r1 + i1 * i1;
            ee[j0] = p0 + p1;
            W0 += pk ? (p1 - p0) : (p0 - p1);
        }
        float e04 = ee[0] + ee[4], e15 = ee[1] + ee[5];
        float e26 = ee[2] + ee[6], e37 = ee[3] + ee[7];
        float T7 = (ee[0] - ee[4]) + (ee[1] - ee[5]) + (ee[2] - ee[6]) + (ee[3] - ee[7]);
        float a0 = e04 + e26, a1 = e15 + e37;
        float T6 = (e04 - e26) + (e15 - e37);
        float T0 = a0 + a1, T5 = a0 - a1;
        if (b8) { T5 = -T5; T6 = -T6; T7 = -T7; W0 = -W0; }

        float acc[16];
        #pragma unroll
        for (int m = 0; m < 16; ++m) {
            if      (m < 5)   acc[m] = ((S >> m) & 1) ? -T5 : T5;
            else if (m == 5)  acc[m] = T5;
            else if (m == 6)  acc[m] = T6;
            else if (m == 7)  acc[m] = T7;
            else if (m < 12)  acc[m] = ((w >> (m - 8)) & 1) ? -T0 : T0;
            else if (m < 15)  acc[m] = ((cc >> (m - 12)) & 1) ? -T0 : T0;
            else              acc[m] = pl ? -W0 : W0;
        }

        #pragma unroll
        for (int m = 0; m < 16; ++m) {
            float v = acc[m];
            #pragma unroll
            for (int o = 16; o > 0; o >>= 1) v += __shfl_xor_sync(0xffffffffu, v, o);
            if (lane == 0) red[m][w] = v;
        }
        __syncthreads();
        if (tid < 16) {
            float s = 0.f;
            #pragma unroll
            for (int k = 0; k < 16; ++k) s += red[tid][k];
            g_part[(b * 8 + cc) * 16 + tid] = s;
        }
        __syncthreads();
    }
}

// per-chain final reduction over its half of the batch
__global__ void kBfin(float* __restrict__ out, int boff) {
    int i = blockIdx.x * blockDim.x + threadIdx.x;
    if (i < HBAT * 16) {
        int b = (i >> 4) + boff, m = i & 15;
        float s = 0.f;
        #pragma unroll
        for (int cc = 0; cc < 8; ++cc) s += g_part[(b * 8 + cc) * 16 + m];
        out[b * 16 + (15 - m)] = s;
    }
}

// ---------------------------------------------------------------------------
extern "C" void kernel_launch(void* const* d_in, const int* in_sizes, int n_in,
                              void* d_out, int out_size) {
    const float* x   = (const float*)d_in[0];
    const float* par = (const float*)d_in[1];
    if (n_in >= 2 && in_sizes[0] == 192) {
        const float* t = x; x = par; par = t;
    }
    float* out = (float*)d_out;

    int nsm = 148;
    cudaDeviceGetAttribute(&nsm, cudaDevAttrMultiProcessorCount, 0);
    const int gpersist = 2 * nsm;

    const size_t smA = 4096 * sizeof(float4) + 32 * sizeof(float);
    cudaFuncSetAttribute(kA, cudaFuncAttributeMaxDynamicSharedMemorySize, (int)smA);

    // Second stream + fork/join events, created once on the first
    // (non-captured correctness) call; reused during graph capture.
    static cudaStream_t s2 = nullptr;
    static cudaEvent_t  evF = nullptr, evJ = nullptr;
    if (s2 == nullptr) {
        cudaStreamCreateWithFlags(&s2, cudaStreamNonBlocking);
        cudaEventCreateWithFlags(&evF, cudaEventDisableTiming);
        cudaEventCreateWithFlags(&evJ, cudaEventDisableTiming);
    }

    cudaStream_t s1 = 0;                      // legacy default (capture) stream

    // fork: s2 depends on everything enqueued so far on s1
    cudaEventRecord(evF, s1);
    cudaStreamWaitEvent(s2, evF, 0);

    // half 0 on s1, half 1 on s2 — independent batch halves
    kB0<<<HBAT, TPB, 0, s1>>>(x, par, 0);
    kB0<<<HBAT, TPB, 0, s2>>>(x, par, HBAT);
    for (int layer = 1; layer < 4; ++layer) {
        kA<<<gpersist, TPB, smA, s1>>>(par, layer, 0);
        kA<<<gpersist, TPB, smA, s2>>>(par, layer, HBAT);
        if (layer < 3) {
            kBmid<<<gpersist, TPB, 0, s1>>>(par, layer, 0);
            kBmid<<<gpersist, TPB, 0, s2>>>(par, layer, HBAT);
        } else {
            kBlast<<<gpersist, TPB, 0, s1>>>(par, layer, 0);
            kBlast<<<gpersist, TPB, 0, s2>>>(par, layer, HBAT);
        }
    }
    // per-chain out-slice reduction on each stream (overlaps the other chain)
    kBfin<<<16, 256, 0, s1>>>(out, 0);
    kBfin<<<16, 256, 0, s2>>>(out, HBAT);

    // join: s1 waits for s2's chain (capture-correct)
    cudaEventRecord(evJ, s2);
    cudaStreamWaitEvent(s1, evJ, 0);
}

// round 16
// speedup vs baseline: 1.0189x; 1.0033x over previous
#include <cuda_runtime.h>
#include <cuda_fp16.h>
#include <math.h>

// ---------------------------------------------------------------------------
// 16-qubit statevector, batch 512. circuit qubit i <-> index bit (15-i).
// Layer = 16 one-qubit gates + CNOT-ladder = suffix-XOR permutation.
// State between passes: __half2(re,im), fp32 compute (f32x2 packed FMA).
// SU(2) gates: 4 floats (u00r,u00i,u01r,u01i); row1 derived inline.
// kA: pack = lo bit 0 (ungated in pass A) -> 8B vector loads/stores, two
//   rgate stages + float4 SMEM exchange; sfx8 perm folded into store address.
// kB: lane = bits 0..4, slots = bits 5..7, pack = b15 (ungated), warp = bits
//   8..11; ladder perm on bits 0..7 + b15-wrap folded into store.
// Batch split in TWO halves (optimum); each half's chain incl. its own
// out-slice reduction runs in its own stream.
// kBlast <Z> epilogue: ONE Walsh butterfly + 4 plain warp sums instead of
// 16 full reductions (25 SHFL vs 80 per thread per tile).
// ---------------------------------------------------------------------------

#define TPB 512
#define BAT 512
#define HBAT 256               // batch elements per chain
#define HTILES 2048            // tiles per chain

typedef unsigned long long u64;

__device__ __half2 g_st[(size_t)BAT * 65536];
__device__ float   g_part[BAT * 8 * 16];

// ---------------- packed f32x2 helpers ----------------
__device__ __forceinline__ u64 pk2(float x, float y) {
    u64 r; asm("mov.b64 %0,{%1,%2};" : "=l"(r) : "f"(x), "f"(y)); return r;
}
__device__ __forceinline__ void upk2(u64 v, float& x, float& y) {
    asm("mov.b64 {%0,%1},%2;" : "=f"(x), "=f"(y) : "l"(v));
}
__device__ __forceinline__ u64 bc2(float x) { return pk2(x, x); }
__device__ __forceinline__ u64 f2mul(u64 a, u64 b) {
    u64 r; asm("mul.rn.f32x2 %0,%1,%2;" : "=l"(r) : "l"(a), "l"(b)); return r;
}
__device__ __forceinline__ u64 f2fma(u64 a, u64 b, u64 c) {
    u64 r; asm("fma.rn.f32x2 %0,%1,%2,%3;" : "=l"(r) : "l"(a), "l"(b), "l"(c)); return r;
}
__device__ __forceinline__ u64 shfl2x(u64 v, int m) {
    float x, y; upk2(v, x, y);
    x = __shfl_xor_sync(0xffffffffu, x, m);
    y = __shfl_xor_sync(0xffffffffu, y, m);
    return pk2(x, y);
}
__device__ __forceinline__ void ld_h2(const __half2* p, float& re, float& im) {
    float2 v = __half22float2(*p); re = v.x; im = v.y;
}
__device__ __forceinline__ void st_h2(__half2* p, float re, float im) {
    *p = __floats2half2_rn(re, im);
}
__device__ __forceinline__ float2 cmulf(float2 a, float2 b) {
    return make_float2(a.x * b.x - a.y * b.y, a.x * b.y + a.y * b.x);
}
__device__ __forceinline__ int sfx5(int v) {
    v ^= v >> 1; v ^= v >> 2; v ^= v >> 4; return v & 31;
}

// SU(2) gate U = Ry(p2)*Rx(p1)*Rz(p0): store row0 only (u00r,u00i,u01r,u01i)
__device__ __forceinline__ void compute_gate4(const float* __restrict__ par,
                                              int layer, int cq, float* uo) {
    const float* pp = par + ((layer * 16 + cq) * 3);
    float sz, cz, sx, cx_, sy, cy;
    sincosf(0.5f * pp[0], &sz, &cz);
    sincosf(0.5f * pp[1], &sx, &cx_);
    sincosf(0.5f * pp[2], &sy, &cy);
    float M00r =  cx_ * cz, M00i = -cx_ * sz;
    float M01r =  sx  * sz, M01i = -sx  * cz;
    float M10r = -sx  * sz, M10i = -sx  * cz;
    float M11r =  cx_ * cz, M11i =  cx_ * sz;
    uo[0] = cy * M00r - sy * M10r;  uo[1] = cy * M00i - sy * M10i;
    uo[2] = cy * M01r - sy * M11r;  uo[3] = cy * M01i - sy * M11i;
}

// packed SU(2) gate on slot bit B
template<int B>
__device__ __forceinline__ void rgateP4(u64* VR, u64* VI, const float* __restrict__ u) {
    const u64 U0 = bc2(u[0]), U1 = bc2(u[1]), N1 = bc2(-u[1]);
    const u64 U2 = bc2(u[2]), N2 = bc2(-u[2]);
    const u64 U3 = bc2(u[3]), N3 = bc2(-u[3]);
    #pragma unroll
    for (int s = 0; s < 8; ++s) if (!(s & B)) {
        u64 ar = VR[s], ai = VI[s], br = VR[s | B], bi = VI[s | B];
        VR[s]     = f2fma(N3, bi, f2fma(U2, br, f2fma(N1, ai, f2mul(U0, ar))));
        VI[s]     = f2fma(U3, br, f2fma(U2, bi, f2fma(U1, ar, f2mul(U0, ai))));
        VR[s | B] = f2fma(U1, bi, f2fma(U0, br, f2fma(N3, ai, f2mul(N2, ar))));
        VI[s | B] = f2fma(N1, br, f2fma(U0, bi, f2fma(U3, ar, f2mul(N2, ai))));
    }
}

// packed SU(2) gate on lane bit j (shfl butterfly)
__device__ __forceinline__ void lgateP4(u64* VR, u64* VI, const float* __restrict__ u,
                                        int lane, int j) {
    const int hi = (lane >> j) & 1;
    const float cai = hi ? -u[1] : u[1];
    const float cbr = hi ? -u[2] : u[2];
    const u64 CAR = bc2(u[0]), CAI = bc2(cai), NAI = bc2(-cai);
    const u64 CBR = bc2(cbr), CBI = bc2(u[3]), NBI = bc2(-u[3]);
    #pragma unroll
    for (int s = 0; s < 8; ++s) {
        u64 pr = shfl2x(VR[s], 1 << j), pi = shfl2x(VI[s], 1 << j);
        u64 nr = f2fma(NBI, pi, f2fma(CBR, pr, f2fma(NAI, VI[s], f2mul(CAR, VR[s]))));
        u64 ni = f2fma(CBI, pr, f2fma(CBR, pi, f2fma(CAI, VR[s], f2mul(CAR, VI[s]))));
        VR[s] = nr; VI[s] = ni;
    }
}

// pass-B gates: rgate bits 5,6,7 + lgate bits 0..4 (pack = b15, never gated)
__device__ __forceinline__ void kb_gates(u64* VR, u64* VI, const float* gU, int lane) {
    rgateP4<1>(VR, VI, gU + 20);
    rgateP4<2>(VR, VI, gU + 24);
    rgateP4<4>(VR, VI, gU + 28);
    #pragma unroll
    for (int j = 0; j < 5; ++j) lgateP4(VR, VI, gU + j * 4, lane, j);
}

// pass-B store with full ladder perm folded in.
__device__ __forceinline__ void kb_store(u64* VR, u64* VI, unsigned base,
                                         int cc, int w, int lane) {
    const int b8 = w & 1;
    const int S  = sfx5(lane);
    const int pl = __popc((unsigned)lane) & 1;
    #pragma unroll
    for (int k = 0; k < 8; ++k) {
        const int pk  = __popc((unsigned)k) & 1;                 // compile-time
        const int s3  = (k ^ (k >> 1) ^ (k >> 2)) & 7;           // sfx3(k), ct
        int flip = pk ^ b8;                                      // warp-uniform
        int dlo  = S ^ (flip ? 31 : 0);
        int dh3  = s3 ^ (b8 ? 7 : 0);
        int d0   = pl ^ flip;                                    // per lane
        float r0, r1, i0, i1;
        upk2(VR[k], r0, r1); upk2(VI[k], i0, i1);
        float Ar = d0 ? r1 : r0, Ai = d0 ? i1 : i0;              // dest b15'=0
        float Br = d0 ? r0 : r1, Bi = d0 ? i0 : i1;              // dest b15'=1
        unsigned a = base | (cc << 12) | (w << 8) | (dh3 << 5) | dlo;
        st_h2(&g_st[a], Ar, Ai);
        st_h2(&g_st[a | 0x8000u], Br, Bi);
    }
}

// ---------------------------------------------------------------------------
// Pass A (layers 1..3), PERSISTENT over one half-batch (2048 tiles).
// Tile = bits {0..4} U {8..15}, c3 = 5..7, pack = bit 0 (ungated).
// ---------------------------------------------------------------------------
__global__ void __launch_bounds__(TPB, 2) kA(const float* __restrict__ par,
                                             int layer, int boff) {
    extern __shared__ float4 buf4[];              // 4096 float4 = 64KB
    float* gUA = (float*)(buf4 + 4096);           // 32 floats

    const int tid = threadIdx.x, lane = tid & 31, w = tid >> 5;
    if (tid < 8) compute_gate4(par, layer, 7 - tid, gUA + tid * 4);  // bit 8+j
    __syncthreads();

    const int llo = lane & 15, bh = lane >> 4;        // bh = b8 (st1) / b12 (st2)
    const int wbase = bh * 256 + w * 16 + llo;        // write: [(k<<1)|b8][w][llo]
    const int rbase = w * 256 + bh * 16 + llo;        // read:  [w][(k<<1)|b12][llo]
    int R = w | (bh << 4);                            // stage2 hi bits 8..12
    int GR = R ^ (R >> 1); GR ^= GR >> 2; GR ^= GR >> 4;  // sfx8(R)

    for (int t = blockIdx.x; t < HTILES; t += gridDim.x) {
        const int c3 = t & 7;
        const unsigned base = (unsigned)((t >> 3) + boff) << 16;
        const unsigned aL = base | (w << 12) | (bh << 8) | (c3 << 5) | (llo << 1);

        u64 VR[8], VI[8];
        #pragma unroll
        for (int k = 0; k < 8; ++k) {
            uint2 raw = *reinterpret_cast<const uint2*>(g_st + (aL | (k << 9)));
            float2 f0 = __half22float2(*reinterpret_cast<__half2*>(&raw.x));
            float2 f1 = __half22float2(*reinterpret_cast<__half2*>(&raw.y));
            VR[k] = pk2(f0.x, f1.x); VI[k] = pk2(f0.y, f1.y);
        }

        // stage1: bits 9,10,11 (rgate) + bit 8 (lane gate j=4)
        rgateP4<1>(VR, VI, gUA + 4);
        rgateP4<2>(VR, VI, gUA + 8);
        rgateP4<4>(VR, VI, gUA + 12);
        lgateP4(VR, VI, gUA + 0, lane, 4);

        __syncthreads();     // buf4 free (prev iteration's readers done)
        #pragma unroll
        for (int k = 0; k < 8; ++k) {
            float r0, r1, i0, i1;
            upk2(VR[k], r0, r1); upk2(VI[k], i0, i1);
            buf4[wbase + k * 512] = make_float4(r0, i0, r1, i1);
        }
        __syncthreads();
        #pragma unroll
        for (int k = 0; k < 8; ++k) {
            float4 v = buf4[rbase + k * 32];
            VR[k] = pk2(v.x, v.z); VI[k] = pk2(v.y, v.w);
        }

        // stage2: bits 13,14,15 (rgate) + bit 12 (lane gate j=4)
        rgateP4<1>(VR, VI, gUA + 20);
        rgateP4<2>(VR, VI, gUA + 24);
        rgateP4<4>(VR, VI, gUA + 28);
        lgateP4(VR, VI, gUA + 16, lane, 4);

        // store: dest hi byte = GR ^ sfx8(k<<5); lo bits unchanged (8B store)
        const unsigned D0 = base | ((unsigned)GR << 8) | (c3 << 5) | (llo << 1);
        #pragma unroll
        for (int k = 0; k < 8; ++k) {
            int e = k << 5; e ^= e >> 1; e ^= e >> 2; e ^= e >> 4;   // ct
            unsigned idx = D0 ^ ((unsigned)e << 8);
            float r0, r1, i0, i1;
            upk2(VR[k], r0, r1); upk2(VI[k], i0, i1);
            __half2 ha = __floats2half2_rn(r0, i0);
            __half2 hb = __floats2half2_rn(r1, i1);
            uint2 o;
            o.x = *reinterpret_cast<unsigned*>(&ha);
            o.y = *reinterpret_cast<unsigned*>(&hb);
            *reinterpret_cast<uint2*>(g_st + idx) = o;
        }
    }
}

// ---------------------------------------------------------------------------
// kB0 (layer 0): ONE CTA PER BATCH ELEMENT of its half. Product tables built
// once, then loop the 8 cc-tiles: synthesize, lo gates, perm-folded store.
// ---------------------------------------------------------------------------
__global__ void __launch_bounds__(TPB, 2) kB0(const float* __restrict__ x,
                                              const float* __restrict__ par,
                                              int boff) {
    __shared__ float4 fv[16];
    __shared__ float  gU[32];
    __shared__ float2 Tlo[256], Thi[256];

    const int tid = threadIdx.x, lane = tid & 31, w = tid >> 5;  // w = bits 8..11
    const int b   = blockIdx.x + boff;
    const unsigned base = (unsigned)b << 16;

    if (tid < 16) {
        int m = tid;                         // index bit m <-> cq 15-m
        float s, c; sincosf(0.5f * x[b * 16 + (15 - m)], &s, &c);
        if (m < 8) {
            fv[m] = make_float4(c, 0.f, 0.f, -s);          // RX|0> = (c, -i s)
        } else {
            float U[4]; compute_gate4(par, 0, 15 - m, U);  // layer-0 hi gate
            fv[m] = make_float4(U[0]*c + U[3]*s, U[1]*c - U[2]*s,
                                -U[2]*c - U[1]*s, U[3]*c - U[0]*s);
        }
    } else if (tid >= 32 && tid < 40) {
        compute_gate4(par, 0, 15 - (tid - 32), gU + (tid - 32) * 4);  // lo gates
    }
    __syncthreads();

    {   // build tables once per batch: 0..255 -> Tlo, 256..511 -> Thi
        int e = tid & 255;
        int mbase = (tid < 256) ? 0 : 8;
        float2 cacc = make_float2(1.f, 0.f);
        #pragma unroll
        for (int m = 0; m < 8; ++m) {
            float4 F = fv[mbase + m];
            float2 bb = ((e >> m) & 1) ? make_float2(F.z, F.w)
                                       : make_float2(F.x, F.y);
            cacc = cmulf(cacc, bb);
        }
        if (tid < 256) {
            Tlo[e] = cacc;
        } else {
            int d = e ^ (e >> 1); d ^= d >> 2; d ^= d >> 4;   // sfx8(e)
            Thi[d & 255] = cacc;                              // Thi[h]=F(inv(h))
        }
    }
    __syncthreads();

    #pragma unroll
    for (int cc = 0; cc < 8; ++cc) {
        u64 VR[8], VI[8];
        float2 H0 = Thi[w | (cc << 4)];
        float2 H1 = Thi[w | (cc << 4) | 128];
        #pragma unroll
        for (int k = 0; k < 8; ++k) {
            float2 L  = Tlo[(k << 5) | lane];
            float2 a0 = cmulf(H0, L), a1 = cmulf(H1, L);
            VR[k] = pk2(a0.x, a1.x); VI[k] = pk2(a0.y, a1.y);
        }
        kb_gates(VR, VI, gU, lane);
        kb_store(VR, VI, base, cc, w, lane);
    }
}

// ---------------------------------------------------------------------------
// kBmid (layers 1,2), PERSISTENT over one half-batch.
// ---------------------------------------------------------------------------
__global__ void __launch_bounds__(TPB, 2) kBmid(const float* __restrict__ par,
                                                int layer, int boff) {
    __shared__ float gU[32];

    const int tid = threadIdx.x, lane = tid & 31, w = tid >> 5;

    if (tid < 8) compute_gate4(par, layer, 15 - tid, gU + tid * 4);
    __syncthreads();

    for (int t = blockIdx.x; t < HTILES; t += gridDim.x) {
        const int cc = t & 7;
        const unsigned base = (unsigned)((t >> 3) + boff) << 16;

        u64 VR[8], VI[8];
        #pragma unroll
        for (int k = 0; k < 8; ++k) {
            unsigned a = base | (cc << 12) | (w << 8) | (k << 5) | lane;
            float r0, i0, r1, i1;
            ld_h2(&g_st[a], r0, i0);
            ld_h2(&g_st[a | 0x8000u], r1, i1);
            VR[k] = pk2(r0, r1); VI[k] = pk2(i0, i1);
        }

        kb_gates(VR, VI, gU, lane);
        kb_store(VR, VI, base, cc, w, lane);
    }
}

// ---------------------------------------------------------------------------
// kBlast (layer 3), PERSISTENT over one half-batch: <Z> partials.
// Epilogue: 4 plain warp sums + ONE signed Walsh butterfly (T5).
// ---------------------------------------------------------------------------
__global__ void __launch_bounds__(TPB, 2) kBlast(const float* __restrict__ par,
                                                 int layer, int boff) {
    __shared__ float gU[32];
    __shared__ float red[16][17];

    const int tid = threadIdx.x, lane = tid & 31, w = tid >> 5;
    const int b8 = w & 1;

    if (tid < 8) compute_gate4(par, layer, 15 - tid, gU + tid * 4);
    __syncthreads();

    const int pl = __popc((unsigned)lane) & 1;

    for (int t = blockIdx.x; t < HTILES; t += gridDim.x) {
        const int cc = t & 7;
        const int b  = (t >> 3) + boff;
        const unsigned base = (unsigned)b << 16;

        u64 VR[8], VI[8];
        #pragma unroll
        for (int k = 0; k < 8; ++k) {
            unsigned a = base | (cc << 12) | (w << 8) | (k << 5) | lane;
            float r0, i0, r1, i1;
            ld_h2(&g_st[a], r0, i0);
            ld_h2(&g_st[a | 0x8000u], r1, i1);
            VR[k] = pk2(r0, r1); VI[k] = pk2(i0, i1);
        }

        kb_gates(VR, VI, gU, lane);

        // packed probabilities; ee indexed by j0 = sfx3(k); W0 with (-1)^par(k)
        float ee[8], W0 = 0.f;
        #pragma unroll
        for (int k = 0; k < 8; ++k) {
            const int j0 = (k ^ (k >> 1) ^ (k >> 2)) & 7;
            const int pk = __popc((unsigned)k) & 1;
            u64 PP = f2fma(VI[k], VI[k], f2mul(VR[k], VR[k]));
            float p0, p1; upk2(PP, p0, p1);
            ee[j0] = p0 + p1;
            W0 += pk ? (p1 - p0) : (p0 - p1);
        }
        float e04 = ee[0] + ee[4], e15 = ee[1] + ee[5];
        float e26 = ee[2] + ee[6], e37 = ee[3] + ee[7];
        float T7 = (ee[0] - ee[4]) + (ee[1] - ee[5]) + (ee[2] - ee[6]) + (ee[3] - ee[7]);
        float a0 = e04 + e26, a1 = e15 + e37;
        float T6 = (e04 - e26) + (e15 - e37);
        float T0 = a0 + a1, T5 = a0 - a1;
        if (b8) { T5 = -T5; T6 = -T6; T7 = -T7; W0 = -W0; }

        // --- warp-level reductions ---
        float A = T0, C6 = T6, C7 = T7;
        float D = pl ? -W0 : W0;
        #pragma unroll
        for (int o = 16; o > 0; o >>= 1) {
            A  += __shfl_xor_sync(0xffffffffu, A,  o);
            C6 += __shfl_xor_sync(0xffffffffu, C6, o);
            C7 += __shfl_xor_sync(0xffffffffu, C7, o);
            D  += __shfl_xor_sync(0xffffffffu, D,  o);
        }
        // signed Walsh butterfly on T5: lane L ends with
        //   sum_l (-1)^{popc(L & l)} T5(l)
        float B = T5;
        #pragma unroll
        for (int j = 0; j < 5; ++j) {
            float tt = __shfl_xor_sync(0xffffffffu, B, 1 << j);
            B = ((lane >> j) & 1) ? (tt - B) : (B + tt);
        }
        // m<5 needs masks {31,30,28,24,16}; m=5 is mask 0 (lane 0).
        if      (lane == 31) red[0][w] = B;
        else if (lane == 30) red[1][w] = B;
        else if (lane == 28) red[2][w] = B;
        else if (lane == 24) red[3][w] = B;
        else if (lane == 16) red[4][w] = B;
        else if (lane == 0) {
            red[5][w]  = B;
            red[6][w]  = C6;
            red[7][w]  = C7;
            red[8][w]  = (w & 1) ? -A : A;
            red[9][w]  = (w & 2) ? -A : A;
            red[10][w] = (w & 4) ? -A : A;
            red[11][w] = (w & 8) ? -A : A;
            red[12][w] = (cc & 1) ? -A : A;
            red[13][w] = (cc & 2) ? -A : A;
            red[14][w] = (cc & 4) ? -A : A;
            red[15][w] = D;
        }
        __syncthreads();
        if (tid < 16) {
            float s = 0.f;
            #pragma unroll
            for (int k = 0; k < 16; ++k) s += red[tid][k];
            g_part[(b * 8 + cc) * 16 + tid] = s;
        }
        __syncthreads();   // red[] reuse guard
    }
}

// per-chain final reduction over its half of the batch
__global__ void kBfin(float* __restrict__ out, int boff) {
    int i = blockIdx.x * blockDim.x + threadIdx.x;
    if (i < HBAT * 16) {
        int b = (i >> 4) + boff, m = i & 15;
        float s = 0.f;
        #pragma unroll
        for (int cc = 0; cc < 8; ++cc) s += g_part[(b * 8 + cc) * 16 + m];
        out[b * 16 + (15 - m)] = s;
    }
}

// ---------------------------------------------------------------------------
extern "C" void kernel_launch(void* const* d_in, const int* in_sizes, int n_in,
                              void* d_out, int out_size) {
    const float* x   = (const float*)d_in[0];
    const float* par = (const float*)d_in[1];
    if (n_in >= 2 && in_sizes[0] == 192) {
        const float* t = x; x = par; par = t;
    }
    float* out = (float*)d_out;

    int nsm = 148;
    cudaDeviceGetAttribute(&nsm, cudaDevAttrMultiProcessorCount, 0);
    const int gpersist = 2 * nsm;

    const size_t smA = 4096 * sizeof(float4) + 32 * sizeof(float);
    cudaFuncSetAttribute(kA, cudaFuncAttributeMaxDynamicSharedMemorySize, (int)smA);

    // Second stream + fork/join events, created once on the first
    // (non-captured correctness) call; reused during graph capture.
    static cudaStream_t s2 = nullptr;
    static cudaEvent_t  evF = nullptr, evJ = nullptr;
    if (s2 == nullptr) {
        cudaStreamCreateWithFlags(&s2, cudaStreamNonBlocking);
        cudaEventCreateWithFlags(&evF, cudaEventDisableTiming);
        cudaEventCreateWithFlags(&evJ, cudaEventDisableTiming);
    }

    cudaStream_t s1 = 0;                      // legacy default (capture) stream

    // fork: s2 depends on everything enqueued so far on s1
    cudaEventRecord(evF, s1);
    cudaStreamWaitEvent(s2, evF, 0);

    // half 0 on s1, half 1 on s2 — independent batch halves
    kB0<<<HBAT, TPB, 0, s1>>>(x, par, 0);
    kB0<<<HBAT, TPB, 0, s2>>>(x, par, HBAT);
    for (int layer = 1; layer < 4; ++layer) {
        kA<<<gpersist, TPB, smA, s1>>>(par, layer, 0);
        kA<<<gpersist, TPB, smA, s2>>>(par, layer, HBAT);
        if (layer < 3) {
            kBmid<<<gpersist, TPB, 0, s1>>>(par, layer, 0);
            kBmid<<<gpersist, TPB, 0, s2>>>(par, layer, HBAT);
        } else {
            kBlast<<<gpersist, TPB, 0, s1>>>(par, layer, 0);
            kBlast<<<gpersist, TPB, 0, s2>>>(par, layer, HBAT);
        }
    }
    // per-chain out-slice reduction on each stream (overlaps the other chain)
    kBfin<<<16, 256, 0, s1>>>(out, 0);
    kBfin<<<16, 256, 0, s2>>>(out, HBAT);

    // join: s1 waits for s2's chain (capture-correct)
    cudaEventRecord(evJ, s2);
    cudaStreamWaitEvent(s1, evJ, 0);
}